// round 14
// baseline (speedup 1.0000x reference)
#include <cuda_runtime.h>
#include <cstdint>

// Problem constants
#define B_    4
#define L_    1024
#define V_    1280
#define E_    768
#define NBIN  8
#define NHID  32

// Output layout: concat(logits[B,L,8,V], tte[B,L,V], mask[B,L,8,V]) fp32
#define TTE_OFF    ((size_t)B_ * L_ * NBIN * V_)                 // 41943040
#define MASK_OFF   (TTE_OFF + (size_t)B_ * L_ * V_)              // 47185920

// Scratch: x = h @ W1, stored m-major as tf32 bit patterns:
// g_x[m*32 + h], m = (b*L+l)*8 + n
__device__ uint32_t g_x[(size_t)B_ * L_ * NBIN * NHID];
// Seed table (16-row granularity)
__device__ int g_seed[(size_t)B_ * 64 * V_];
// Precomputed W1 hi/lo tf32 split (768 x 256 each)
__device__ uint32_t g_W1h[E_ * 256];
__device__ uint32_t g_W1l[E_ * 256];

typedef unsigned long long u64;

__device__ __forceinline__ uint32_t to_tf32(float f) {
    uint32_t r; asm("cvt.rna.tf32.f32 %0, %1;" : "=r"(r) : "f"(f)); return r;
}

// ---------------------------------------------------------------------------
// Kernel 0: W1 -> hi/lo tf32 split, once.  49152 float4, grid 192 x 256.
// ---------------------------------------------------------------------------
__global__ __launch_bounds__(256) void k_prep(const float* __restrict__ W1) {
    int i = blockIdx.x * 256 + threadIdx.x;      // 0..49151
    float4 v = ((const float4*)W1)[i];
    uint32_t hx = to_tf32(v.x), hy = to_tf32(v.y),
             hz = to_tf32(v.z), hw = to_tf32(v.w);
    ((uint4*)g_W1h)[i] = make_uint4(hx, hy, hz, hw);
    ((uint4*)g_W1l)[i] = make_uint4(to_tf32(v.x - __uint_as_float(hx)),
                                    to_tf32(v.y - __uint_as_float(hy)),
                                    to_tf32(v.z - __uint_as_float(hz)),
                                    to_tf32(v.w - __uint_as_float(hw)));
}

// ---------------------------------------------------------------------------
// Kernel 1: x = h @ W1 via mma.sync tf32, 3-term split (near-fp32 exact).
// M=4096, N=256, K=768.  Block 64m x 64n, 256 thr, 8 warps (4wm x 2wv),
// warp tile 16m x 32n, K-chunks of 32.  Grid (4, 64) = 256 blocks.
// Re-warped from 4->8 warps/block for occupancy (R13: occ 10.6%, regs 128).
// ---------------------------------------------------------------------------
__global__ __launch_bounds__(256) void k_gemm1t(const float* __restrict__ A) {
    __shared__ uint32_t Ah[64][36], Al[64][36];   // pad 36: banks 4g+l4
    __shared__ uint32_t Bh[32][72], Bl[32][72];   // pad 72: banks 8l4+g
    int tid = threadIdx.x;
    int lane = tid & 31, wid = tid >> 5;
    int g = lane >> 2, l4 = lane & 3;
    int colBase = blockIdx.x * 64;      // 0..3
    int rowBase = blockIdx.y * 64;      // 0..63
    int wm = wid & 3, wv = wid >> 2;    // 4 m-warps x 2 n-warps

    float c[4][4];
#pragma unroll
    for (int vt = 0; vt < 4; vt++)
#pragma unroll
        for (int q = 0; q < 4; q++) c[vt][q] = 0.0f;

    for (int k0 = 0; k0 < E_; k0 += 32) {
        // A chunk: 64 x 32 fp32 -> hi/lo tf32  (512 float4, 2 per thread)
#pragma unroll
        for (int p = 0; p < 2; p++) {
            int idx = tid + p * 256;
            int r = idx >> 3, c4 = (idx & 7) << 2;
            float4 v = *(const float4*)&A[(size_t)(rowBase + r) * E_ + k0 + c4];
            uint32_t hx = to_tf32(v.x), hy = to_tf32(v.y),
                     hz = to_tf32(v.z), hw = to_tf32(v.w);
            Ah[r][c4+0] = hx; Ah[r][c4+1] = hy; Ah[r][c4+2] = hz; Ah[r][c4+3] = hw;
            Al[r][c4+0] = to_tf32(v.x - __uint_as_float(hx));
            Al[r][c4+1] = to_tf32(v.y - __uint_as_float(hy));
            Al[r][c4+2] = to_tf32(v.z - __uint_as_float(hz));
            Al[r][c4+3] = to_tf32(v.w - __uint_as_float(hw));
        }
        // B chunk: 32 x 64 pre-split tf32 (512 uint4 per buffer, 2 each)
#pragma unroll
        for (int p = 0; p < 2; p++) {
            int idx = tid + p * 256;
            int kr = idx >> 4, c4 = (idx & 15) << 2;
            size_t goff = ((size_t)(k0 + kr) * 256 + colBase + c4) >> 2;
            *(uint4*)&Bh[kr][c4] = ((const uint4*)g_W1h)[goff];
            *(uint4*)&Bl[kr][c4] = ((const uint4*)g_W1l)[goff];
        }
        __syncthreads();

#pragma unroll
        for (int ks = 0; ks < 4; ks++) {
            int kk = ks * 8;
            int rb = wm * 16;
            uint32_t ah[4], al[4], bh[4][2], bl[4][2];
            ah[0] = Ah[rb + g][kk + l4];
            ah[1] = Ah[rb + g + 8][kk + l4];
            ah[2] = Ah[rb + g][kk + l4 + 4];
            ah[3] = Ah[rb + g + 8][kk + l4 + 4];
            al[0] = Al[rb + g][kk + l4];
            al[1] = Al[rb + g + 8][kk + l4];
            al[2] = Al[rb + g][kk + l4 + 4];
            al[3] = Al[rb + g + 8][kk + l4 + 4];
#pragma unroll
            for (int vt = 0; vt < 4; vt++) {
                int cb = wv * 32 + vt * 8 + g;
                bh[vt][0] = Bh[kk + l4][cb];
                bh[vt][1] = Bh[kk + l4 + 4][cb];
                bl[vt][0] = Bl[kk + l4][cb];
                bl[vt][1] = Bl[kk + l4 + 4][cb];
            }
#pragma unroll
            for (int vt = 0; vt < 4; vt++) {
                asm volatile(
                    "mma.sync.aligned.m16n8k8.row.col.f32.tf32.tf32.f32 "
                    "{%0,%1,%2,%3}, {%4,%5,%6,%7}, {%8,%9}, {%0,%1,%2,%3};"
                    : "+f"(c[vt][0]), "+f"(c[vt][1]),
                      "+f"(c[vt][2]), "+f"(c[vt][3])
                    : "r"(ah[0]), "r"(ah[1]), "r"(ah[2]), "r"(ah[3]),
                      "r"(bh[vt][0]), "r"(bh[vt][1]));
                asm volatile(
                    "mma.sync.aligned.m16n8k8.row.col.f32.tf32.tf32.f32 "
                    "{%0,%1,%2,%3}, {%4,%5,%6,%7}, {%8,%9}, {%0,%1,%2,%3};"
                    : "+f"(c[vt][0]), "+f"(c[vt][1]),
                      "+f"(c[vt][2]), "+f"(c[vt][3])
                    : "r"(ah[0]), "r"(ah[1]), "r"(ah[2]), "r"(ah[3]),
                      "r"(bl[vt][0]), "r"(bl[vt][1]));
                asm volatile(
                    "mma.sync.aligned.m16n8k8.row.col.f32.tf32.tf32.f32 "
                    "{%0,%1,%2,%3}, {%4,%5,%6,%7}, {%8,%9}, {%0,%1,%2,%3};"
                    : "+f"(c[vt][0]), "+f"(c[vt][1]),
                      "+f"(c[vt][2]), "+f"(c[vt][3])
                    : "r"(al[0]), "r"(al[1]), "r"(al[2]), "r"(al[3]),
                      "r"(bh[vt][0]), "r"(bh[vt][1]));
            }
        }
        __syncthreads();
    }

    // Epilogue: write x as tf32 to g_x m-major.
    int r0 = rowBase + wm * 16 + g;
#pragma unroll
    for (int vt = 0; vt < 4; vt++) {
        int col = colBase + wv * 32 + vt * 8 + 2 * l4;
        int n = col >> 5, hh = col & 31;
        uint2 q0 = make_uint2(to_tf32(c[vt][0]), to_tf32(c[vt][1]));
        uint2 q1 = make_uint2(to_tf32(c[vt][2]), to_tf32(c[vt][3]));
        *(uint2*)&g_x[((size_t)r0 * 8 + n) * 32 + hh] = q0;
        *(uint2*)&g_x[((size_t)(r0 + 8) * 8 + n) * 32 + hh] = q1;
    }
}

// ---------------------------------------------------------------------------
// Kernel 2a: seed scan, 16-row granularity.  grid (vb=5, b=4), 256 threads.
// ---------------------------------------------------------------------------
__global__ __launch_bounds__(256) void k_seed(const int* __restrict__ targets) {
    __shared__ int tg[L_];
    int b = blockIdx.y;
    int v = blockIdx.x * 256 + threadIdx.x;
    for (int i = threadIdx.x; i < L_; i += 256)
        tg[i] = targets[(size_t)b * L_ + i];
    __syncthreads();

    int* seed = g_seed + (size_t)b * 64 * V_;
    int nxt = L_;
#pragma unroll 1
    for (int ch = 63; ch >= 0; --ch) {
        seed[(size_t)ch * V_ + v] = nxt;   // occurrences at index >= (ch+1)*16
#pragma unroll
        for (int ii = 15; ii >= 0; --ii) {
            int i = ch * 16 + ii;
            if (tg[i] == v) nxt = i;
        }
    }
}

// ---------------------------------------------------------------------------
// Kernel 2b: tte + mask writer.  grid (chunk=64, b=4), 320 threads,
// 4 consecutive v per thread, 16 rows per block; STG.128 only.
// Special case (scatter semantics): token_index[b, i>=1, v=0] = 0.
// ---------------------------------------------------------------------------
__global__ __launch_bounds__(320) void k_tte_write(const int* __restrict__ targets,
                                                   const float* __restrict__ age,
                                                   const float* __restrict__ targets_age,
                                                   float* __restrict__ out) {
    __shared__ float ta[L_];
    __shared__ float ag_s[16];
    __shared__ int   tg_s[16];

    int b     = blockIdx.y;
    int chunk = blockIdx.x;          // 0..63
    int i0    = chunk * 16;
    int tid   = threadIdx.x;
    int v0    = 4 * tid;             // 0..1276

    if (tid < 256)
        ((float4*)ta)[tid] = ((const float4*)(targets_age + (size_t)b * L_))[tid];
    if (tid < 16) {
        ag_s[tid] = age[(size_t)b * L_ + i0 + tid];
        tg_s[tid] = targets[(size_t)b * L_ + i0 + tid];
    }
    __syncthreads();

    int4 sd = *(const int4*)&g_seed[((size_t)b * 64 + chunk) * V_ + v0];
    int nxt[4] = {sd.x, sd.y, sd.z, sd.w};

    float* out_tte  = out + TTE_OFF  + (size_t)b * L_ * V_;
    float* out_mask = out + MASK_OFF + (size_t)b * L_ * NBIN * V_;
    bool isv0 = (v0 == 0);

#pragma unroll 1
    for (int ii = 15; ii >= 0; --ii) {
        int i = i0 + ii;
        int t = tg_s[ii];
#pragma unroll
        for (int k = 0; k < 4; k++)
            if (t == v0 + k) nxt[k] = i;

        float a = ag_s[ii];
        float tt[4]; bool ne[4];
#pragma unroll
        for (int k = 0; k < 4; k++) {
            int idx = nxt[k];
            if (isv0 && k == 0 && i >= 1) idx = 0;
            ne[k] = (idx == L_);
            tt[k] = ta[ne[k] ? (L_ - 1) : idx] - a;
        }
        *(float4*)&out_tte[(size_t)i * V_ + v0] = make_float4(tt[0], tt[1], tt[2], tt[3]);

        size_t mbase = (size_t)i * NBIN * V_ + v0;
#pragma unroll
        for (int n = 0; n < NBIN; n++) {
            float lo = 1.25f * n;
            float hi = lo + 1.25f;
            float4 m;
            m.x = ((tt[0] >= lo && tt[0] < hi) || ne[0]) ? 1.0f : 0.0f;
            m.y = ((tt[1] >= lo && tt[1] < hi) || ne[1]) ? 1.0f : 0.0f;
            m.z = ((tt[2] >= lo && tt[2] < hi) || ne[2]) ? 1.0f : 0.0f;
            m.w = ((tt[3] >= lo && tt[3] < hi) || ne[3]) ? 1.0f : 0.0f;
            *(float4*)&out_mask[mbase + (size_t)n * V_] = m;
        }
    }
}

// ---------------------------------------------------------------------------
// Kernel 3: logits GEMM via mma.sync tf32 (validated R10-R13, unchanged).
// M=32768, N=1280, K=32.  Block 256 thr, tile 128m x 64v; warp tile 32m x 32v.
// ---------------------------------------------------------------------------
__global__ __launch_bounds__(256) void k_gemm2m(const float* __restrict__ W2,
                                                float* __restrict__ out) {
    __shared__ uint32_t As[128][36];
    __shared__ uint32_t Bs[32][72];
    int tid = threadIdx.x;
    int lane = tid & 31, wid = tid >> 5;
    int g = lane >> 2, l4 = lane & 3;
    int v0 = blockIdx.x * 64;          // 0..19
    int m0 = blockIdx.y * 128;         // 0..255
    int wm = wid & 3, wv = wid >> 2;

    const uint4* xsrc = (const uint4*)(g_x + (size_t)m0 * 32);
#pragma unroll
    for (int p = 0; p < 4; p++) {
        int idx = tid + p * 256;           // 1024 uint4
        uint4 q = xsrc[idx];
        int row = idx >> 3, c4 = (idx & 7) << 2;
        *(uint4*)&As[row][c4] = q;
    }
#pragma unroll
    for (int p = 0; p < 2; p++) {
        int idx = tid + p * 256;           // 512 float4
        int hh = idx >> 4, v4 = (idx & 15) << 2;
        float4 w = *(const float4*)&W2[(size_t)hh * V_ + v0 + v4];
        uint4 q = make_uint4(to_tf32(w.x), to_tf32(w.y), to_tf32(w.z), to_tf32(w.w));
        *(uint4*)&Bs[hh][v4] = q;
    }
    __syncthreads();

    float c[2][4][4];
#pragma unroll
    for (int mt = 0; mt < 2; mt++)
#pragma unroll
        for (int vt = 0; vt < 4; vt++)
#pragma unroll
            for (int q = 0; q < 4; q++) c[mt][vt][q] = 0.0f;

#pragma unroll
    for (int k = 0; k < 4; k++) {
        int kk = k * 8;
        uint32_t a[2][4], b[4][2];
#pragma unroll
        for (int mt = 0; mt < 2; mt++) {
            int rb = wm * 32 + mt * 16;
            a[mt][0] = As[rb + g][kk + l4];
            a[mt][1] = As[rb + g + 8][kk + l4];
            a[mt][2] = As[rb + g][kk + l4 + 4];
            a[mt][3] = As[rb + g + 8][kk + l4 + 4];
        }
#pragma unroll
        for (int vt = 0; vt < 4; vt++) {
            int cb = wv * 32 + vt * 8 + g;
            b[vt][0] = Bs[kk + l4][cb];
            b[vt][1] = Bs[kk + l4 + 4][cb];
        }
#pragma unroll
        for (int mt = 0; mt < 2; mt++)
#pragma unroll
            for (int vt = 0; vt < 4; vt++)
                asm volatile(
                    "mma.sync.aligned.m16n8k8.row.col.f32.tf32.tf32.f32 "
                    "{%0,%1,%2,%3}, {%4,%5,%6,%7}, {%8,%9}, {%0,%1,%2,%3};"
                    : "+f"(c[mt][vt][0]), "+f"(c[mt][vt][1]),
                      "+f"(c[mt][vt][2]), "+f"(c[mt][vt][3])
                    : "r"(a[mt][0]), "r"(a[mt][1]), "r"(a[mt][2]), "r"(a[mt][3]),
                      "r"(b[vt][0]), "r"(b[vt][1]));
    }

#pragma unroll
    for (int mt = 0; mt < 2; mt++) {
        int r0 = m0 + wm * 32 + mt * 16 + g;
#pragma unroll
        for (int vt = 0; vt < 4; vt++) {
            int cc = v0 + wv * 32 + vt * 8 + 2 * l4;
            *(float2*)&out[(size_t)r0 * V_ + cc] =
                make_float2(c[mt][vt][0], c[mt][vt][1]);
            *(float2*)&out[(size_t)(r0 + 8) * V_ + cc] =
                make_float2(c[mt][vt][2], c[mt][vt][3]);
        }
    }
}

// ---------------------------------------------------------------------------
static cudaStream_t g_s2;
static cudaEvent_t g_e1, g_e2;
static struct StreamInit {
    StreamInit() {
        cudaStreamCreateWithFlags(&g_s2, cudaStreamNonBlocking);
        cudaEventCreateWithFlags(&g_e1, cudaEventDisableTiming);
        cudaEventCreateWithFlags(&g_e2, cudaEventDisableTiming);
    }
} g_stream_init;

extern "C" void kernel_launch(void* const* d_in, const int* in_sizes, int n_in,
                              void* d_out, int out_size) {
    const float* h       = (const float*)d_in[0];  // (B,L,768)
    const float* age     = (const float*)d_in[1];  // (B,L)
    const float* tage    = (const float*)d_in[2];  // (B,L)
    const int*   targets = (const int*)d_in[4];    // (B,L) int32
    const float* W1      = (const float*)d_in[5];  // (768,256)
    const float* W2      = (const float*)d_in[6];  // (32,1280)
    float* out = (float*)d_out;

    // Fork: seed -> tte_write on stream 2; prep -> gemm1t -> gemm2m on 0.
    cudaEventRecord(g_e1, 0);
    cudaStreamWaitEvent(g_s2, g_e1, 0);
    k_seed<<<dim3(5, B_), 256, 0, g_s2>>>(targets);
    k_tte_write<<<dim3(64, B_), 320, 0, g_s2>>>(targets, age, tage, out);
    cudaEventRecord(g_e2, g_s2);

    k_prep<<<192, 256>>>(W1);
    k_gemm1t<<<dim3(4, 64), 256>>>(h);
    k_gemm2m<<<dim3(20, 256), 256>>>(W2, out);
    cudaStreamWaitEvent(0, g_e2, 0);
}